// round 7
// baseline (speedup 1.0000x reference)
#include <cuda_runtime.h>
#include <cuda_bf16.h>
#include <math.h>
#include <stdint.h>

// Problem constants
#define BB 2
#define CC 256
#define NN 4096
#define RR 8
#define GG 4
#define CG 64   // C / G

// Scratch (static device globals: allocation-free rule)
__device__ float g_qkT[4][BB][NN][RR];   // p: 0=qL,1=kU,2=qU,3=kL; [n][r]
__device__ float g_v[2][BB][CC][NN];     // d=0 vU(fU) for LU, d=1 vL(fL) for UL
__device__ float g_lz[2][BB][NN];        // -log( sum_m exp(S[n,m]) )

// ---------------------------------------------------------------------------
// helpers
// ---------------------------------------------------------------------------
__device__ __forceinline__ uint32_t bf2(float lo, float hi) {
    uint32_t r;
    asm("cvt.rn.bf16x2.f32 %0, %1, %2;" : "=r"(r) : "f"(hi), "f"(lo));
    return r;
}

__device__ __forceinline__ void mma_bf16(float* c, uint32_t a0, uint32_t a1,
                                         uint32_t a2, uint32_t a3,
                                         uint32_t b0, uint32_t b1) {
    asm volatile(
        "mma.sync.aligned.m16n8k16.row.col.f32.bf16.bf16.f32 "
        "{%0,%1,%2,%3}, {%4,%5,%6,%7}, {%8,%9}, {%0,%1,%2,%3};\n"
        : "+f"(c[0]), "+f"(c[1]), "+f"(c[2]), "+f"(c[3])
        : "r"(a0), "r"(a1), "r"(a2), "r"(a3), "r"(b0), "r"(b1));
}

__device__ __forceinline__ float dot8(float4 qa, float4 qb, float4 ka, float4 kb) {
    float s = qa.x * ka.x;
    s = fmaf(qa.y, ka.y, s); s = fmaf(qa.z, ka.z, s); s = fmaf(qa.w, ka.w, s);
    s = fmaf(qb.x, kb.x, s); s = fmaf(qb.y, kb.y, s);
    s = fmaf(qb.z, kb.z, s); s = fmaf(qb.w, kb.w, s);
    return s;
}

// ---------------------------------------------------------------------------
// K1: fused rank-8 projections, 4-way C-split per block.
// grid (NN/64, BB) = 128 blocks, block 256.
// ---------------------------------------------------------------------------
__global__ __launch_bounds__(256) void k_proj(
    const float* __restrict__ fL, const float* __restrict__ fU,
    const float* __restrict__ qLw, const float* __restrict__ qLb,
    const float* __restrict__ kUw, const float* __restrict__ kUb,
    const float* __restrict__ qUw, const float* __restrict__ qUb,
    const float* __restrict__ kLw, const float* __restrict__ kLb)
{
    __shared__ float ws[4][RR * CC];     // 32 KB; reused as reduction buffer
    int tid = threadIdx.x;
    for (int i = tid; i < RR * CC; i += 256) {
        ws[0][i] = qLw[i];
        ws[1][i] = kUw[i];
        ws[2][i] = qUw[i];
        ws[3][i] = kLw[i];
    }
    __syncthreads();

    int b  = blockIdx.y;
    int nn = tid & 63;
    int cs = tid >> 6;
    int n  = blockIdx.x * 64 + nn;
    const float* xl = fL + (size_t)b * CC * NN + n;
    const float* xu = fU + (size_t)b * CC * NN + n;

    float a0[RR], a1[RR], a2[RR], a3[RR];
#pragma unroll
    for (int r = 0; r < RR; r++) { a0[r] = a1[r] = a2[r] = a3[r] = 0.f; }

    int cbase = cs * 64;
    for (int cc = 0; cc < 64; cc++) {
        int c = cbase + cc;
        float lx = xl[(size_t)c * NN];
        float ux = xu[(size_t)c * NN];
#pragma unroll
        for (int r = 0; r < RR; r++) {
            a0[r] = fmaf(ws[0][r * CC + c], lx, a0[r]);
            a1[r] = fmaf(ws[1][r * CC + c], ux, a1[r]);
            a2[r] = fmaf(ws[2][r * CC + c], ux, a2[r]);
            a3[r] = fmaf(ws[3][r * CC + c], lx, a3[r]);
        }
    }
    __syncthreads();
    float* red = &ws[0][0];               // [3][64][33] padded
    if (cs > 0) {
        float* rp = red + (size_t)(cs - 1) * 64 * 33 + nn * 33;
#pragma unroll
        for (int r = 0; r < RR; r++) {
            rp[r]      = a0[r];
            rp[8 + r]  = a1[r];
            rp[16 + r] = a2[r];
            rp[24 + r] = a3[r];
        }
    }
    __syncthreads();
    if (cs == 0) {
#pragma unroll
        for (int t = 0; t < 3; t++) {
            float* rp = red + (size_t)t * 64 * 33 + nn * 33;
#pragma unroll
            for (int r = 0; r < RR; r++) {
                a0[r] += rp[r];
                a1[r] += rp[8 + r];
                a2[r] += rp[16 + r];
                a3[r] += rp[24 + r];
            }
        }
        float* t0 = &g_qkT[0][b][n][0];
        float* t1 = &g_qkT[1][b][n][0];
        float* t2 = &g_qkT[2][b][n][0];
        float* t3 = &g_qkT[3][b][n][0];
#pragma unroll
        for (int r = 0; r < RR; r++) {
            t0[r] = a0[r] + qLb[r];
            t1[r] = a1[r] + kUb[r];
            t2[r] = a2[r] + qUb[r];
            t3[r] = a3[r] + kLb[r];
        }
    }
}

// ---------------------------------------------------------------------------
// K2: grouped 1x1x1 v-conv. grid (NN/128, GG, 2*BB), block 128.
// ---------------------------------------------------------------------------
__global__ __launch_bounds__(128) void k_vconv(
    const float* __restrict__ fL, const float* __restrict__ fU,
    const float* __restrict__ vUw, const float* __restrict__ vUb,
    const float* __restrict__ vLw, const float* __restrict__ vLb)
{
    int z = blockIdx.z;
    int d = z >> 1;
    int b = z & 1;
    int g = blockIdx.y;
    int tid = threadIdx.x;
    int n = blockIdx.x * 128 + tid;

    const float* x    = (d == 0) ? fU  : fL;
    const float* wsrc = (d == 0) ? vUw : vLw;
    const float* bsrc = (d == 0) ? vUb : vLb;

    __shared__ float wT[CG][CG];
    for (int i = tid; i < CG * CG; i += 128) {
        int co = i / CG, ci = i % CG;
        wT[ci][co] = wsrc[(g * CG + co) * CG + ci];
    }
    __syncthreads();

    float acc[CG];
#pragma unroll
    for (int co = 0; co < CG; co++) acc[co] = 0.f;

    const float* xp = x + ((size_t)b * CC + g * CG) * NN + n;
    for (int ci = 0; ci < CG; ci++) {
        float xv = xp[(size_t)ci * NN];
#pragma unroll
        for (int co = 0; co < CG; co++)
            acc[co] = fmaf(wT[ci][co], xv, acc[co]);
    }
#pragma unroll
    for (int co = 0; co < CG; co++)
        g_v[d][b][g * CG + co][n] = acc[co] + bsrc[g * CG + co];
}

// ---------------------------------------------------------------------------
// K3: softmax log-normalizers. Each warp owns 4 rows (q in registers), so
// k traffic is amortized 4x; the 8 warps of a block reuse k via L1.
// grid (NN/32, BB, 2) = 512 blocks, block 256.
// ---------------------------------------------------------------------------
__global__ __launch_bounds__(256) void k_softstats()
{
    int d = blockIdx.z, b = blockIdx.y;
    int tid = threadIdx.x;
    int warp = tid >> 5, lane = tid & 31;
    int row0 = blockIdx.x * 32 + warp * 4;
    int qi = d ? 2 : 0;
    int ki = d ? 3 : 1;

    float4 qa[4], qb[4];
#pragma unroll
    for (int rr = 0; rr < 4; rr++) {
        const float4* qp = (const float4*)&g_qkT[qi][b][row0 + rr][0];
        qa[rr] = qp[0];
        qb[rr] = qp[1];
    }
    const float4* kbase = (const float4*)&g_qkT[ki][b][0][0];

    float sm[4] = {0.f, 0.f, 0.f, 0.f};
    for (int m = lane; m < NN; m += 32) {
        float4 ka = kbase[2 * m];
        float4 kc = kbase[2 * m + 1];
#pragma unroll
        for (int rr = 0; rr < 4; rr++)
            sm[rr] += __expf(dot8(qa[rr], qb[rr], ka, kc));
    }
#pragma unroll
    for (int rr = 0; rr < 4; rr++) {
#pragma unroll
        for (int o = 16; o > 0; o >>= 1)
            sm[rr] += __shfl_xor_sync(0xffffffffu, sm[rr], o);
    }
    if (lane == 0) {
#pragma unroll
        for (int rr = 0; rr < 4; rr++)
            g_lz[d][b][row0 + rr] = -__logf(sm[rr]);
    }
}

// ---------------------------------------------------------------------------
// K4: bf16 mma.sync GEMM  out[c,m] = f[c,m] + beta * sum_n V[c,n]*A[n,m]
// A[n,m] = exp(q[n].k[m] + lz[n]) regenerated in SMEM per K-step.
// Block: 512 thr (16 warps), tile 128(C) x 128(m), KT=32 (2 k16-groups).
// Warp tile 32x32: 2 M-tiles x 4 N-tiles of m16n8k16 -> acc = 32 regs.
// Double-buffered pipeline: [stage(j+1); regen(j)] bar [mma(j)] bar.
// grid (NN/128, 2 c-halves, 4 bd) = 256 blocks.
// ---------------------------------------------------------------------------
#define KT 32
#define MT 128
#define CT 128

__global__ __launch_bounds__(512) void k_attn_out_tc(
    const float* __restrict__ fL, const float* __restrict__ fU,
    const float* __restrict__ betap, float* __restrict__ out)
{
    __shared__ uint2 VB[2][2][CT * 4];   // [buf][g][c*4+slot]  16 KB
    __shared__ uint2 AB[2][MT * 4];      // [g][m*4+slot]        8 KB
    __shared__ float Qb[2][256];         // [buf][k*8+r]         2 KB
    __shared__ float Lzb[2][32];
    __shared__ float Ksh[MT * RR];       // [m*8+r]              4 KB

    int d = blockIdx.z >> 1, b = blockIdx.z & 1;
    int ch = blockIdx.y;
    int m0 = blockIdx.x * MT;
    int c_base = ch * CT;
    int qi = d ? 2 : 0, ki = d ? 3 : 1;

    int tid  = threadIdx.x;
    int warp = tid >> 5, lane = tid & 31;
    int wy = warp >> 2, wx = warp & 3;   // 4 warps along C, 4 along m
    int cw = wy * 32, mw = wx * 32;
    int lr = lane >> 2, lc = lane & 3;

    const float* qsrc  = &g_qkT[qi][b][0][0];
    const float* lzsrc = &g_lz[d][b][0];

    // staging role: c = c_base + (tid&127); s = tid>>7 -> (g, k-half)
    int cst = tid & 127;
    int sgs = (tid >> 8) & 1;            // g
    int shk = (tid >> 7) & 1;            // k-half within g
    const float* vrow = &g_v[d][b][c_base + cst][0];
    int sl0 = ((2 * shk)     + cst + (cst >> 2)) & 3;
    int sl1 = ((2 * shk + 1) + cst + (cst >> 2)) & 3;

    // regen role: rp = tid&3 (k-pair), rm = tid>>2 (m row)
    int rp = tid & 3;
    int rm = (tid >> 2) & 127;
    int asl = (rp + rm + (rm >> 2)) & 3;

    // K for A-regen (contiguous 4 KB)
    {
        const float* ksrc = &g_qkT[ki][b][m0][0];
        for (int i = tid; i < MT * RR; i += 512) Ksh[i] = ksrc[i];
    }

    // fragment offsets
    int aoff[2][2];
#pragma unroll
    for (int mt = 0; mt < 2; mt++) {
        int c0 = cw + mt * 16 + lr;
        int c1 = c0 + 8;
        aoff[mt][0] = c0 * 4 + ((lc + c0 + (c0 >> 2)) & 3);
        aoff[mt][1] = c1 * 4 + ((lc + c1 + (c1 >> 2)) & 3);
    }
    int boff[4];
#pragma unroll
    for (int nt = 0; nt < 4; nt++) {
        int n = mw + nt * 8 + lr;
        boff[nt] = n * 4 + ((lc + n + (n >> 2)) & 3);
    }

    float acc[2][4][4];
#pragma unroll
    for (int mt = 0; mt < 2; mt++)
#pragma unroll
        for (int nt = 0; nt < 4; nt++)
#pragma unroll
            for (int q = 0; q < 4; q++) acc[mt][nt][q] = 0.f;

#define STAGE(J) do {                                                          \
    int bu = (J) & 1; int n0 = (J) * KT;                                       \
    const float4* vp = (const float4*)(vrow + n0);                             \
    float4 pa = vp[4 * sgs + shk];                                             \
    float4 pb = vp[4 * sgs + 2 + shk];                                         \
    uint2* dst = VB[bu][sgs] + cst * 4;                                        \
    dst[sl0] = make_uint2(bf2(pa.x, pa.y), bf2(pb.x, pb.y));                   \
    dst[sl1] = make_uint2(bf2(pa.z, pa.w), bf2(pb.z, pb.w));                   \
    if (tid < 256) Qb[bu][tid] = qsrc[n0 * 8 + tid];                           \
    else if (tid < 288) Lzb[bu][tid - 256] = lzsrc[n0 + tid - 256];            \
} while (0)

#define REGEN_G(J, G) do {                                                     \
    int bu = (J) & 1;                                                          \
    const float* qb = Qb[bu];                                                  \
    int k0 = (G) * 16 + 2 * rp;                                                \
    float4 q0a = *(const float4*)&qb[k0 * 8];                                  \
    float4 q0b = *(const float4*)&qb[k0 * 8 + 4];                              \
    float4 q1a = *(const float4*)&qb[(k0 + 1) * 8];                            \
    float4 q1b = *(const float4*)&qb[(k0 + 1) * 8 + 4];                        \
    float4 q2a = *(const float4*)&qb[(k0 + 8) * 8];                            \
    float4 q2b = *(const float4*)&qb[(k0 + 8) * 8 + 4];                        \
    float4 q3a = *(const float4*)&qb[(k0 + 9) * 8];                            \
    float4 q3b = *(const float4*)&qb[(k0 + 9) * 8 + 4];                        \
    float z0 = Lzb[bu][k0],     z1 = Lzb[bu][k0 + 1];                          \
    float z2 = Lzb[bu][k0 + 8], z3 = Lzb[bu][k0 + 9];                          \
    float4 ka = *(const float4*)&Ksh[rm * 8];                                  \
    float4 kb = *(const float4*)&Ksh[rm * 8 + 4];                              \
    float e0 = __expf(dot8(q0a, q0b, ka, kb) + z0);                            \
    float e1 = __expf(dot8(q1a, q1b, ka, kb) + z1);                            \
    float e2 = __expf(dot8(q2a, q2b, ka, kb) + z2);                            \
    float e3 = __expf(dot8(q3a, q3b, ka, kb) + z3);                            \
    AB[G][rm * 4 + asl] = make_uint2(bf2(e0, e1), bf2(e2, e3));                \
} while (0)

#define MMA_G(J, G) do {                                                       \
    int bu = (J) & 1;                                                          \
    const uint2* vr = VB[bu][G];                                               \
    const uint2* ar = AB[G];                                                   \
    uint2 av[2][2];                                                            \
    _Pragma("unroll")                                                          \
    for (int mt = 0; mt < 2; mt++) {                                           \
        av[mt][0] = vr[aoff[mt][0]];                                           \
        av[mt][1] = vr[aoff[mt][1]];                                           \
    }                                                                          \
    _Pragma("unroll")                                                          \
    for (int nt = 0; nt < 4; nt++) {                                           \
        uint2 bb = ar[boff[nt]];                                               \
        _Pragma("unroll")                                                      \
        for (int mt = 0; mt < 2; mt++)                                         \
            mma_bf16(acc[mt][nt], av[mt][0].x, av[mt][1].x,                    \
                     av[mt][0].y, av[mt][1].y, bb.x, bb.y);                    \
    }                                                                          \
} while (0)

    STAGE(0);
    __syncthreads();

    for (int j = 0; j < NN / KT; j++) {
        if (j + 1 < NN / KT) STAGE(j + 1);
        REGEN_G(j, 0);
        REGEN_G(j, 1);
        __syncthreads();
        MMA_G(j, 0);
        MMA_G(j, 1);
        __syncthreads();
    }

    // epilogue: out = f + beta * acc
    float beta = *betap;
    const float* fsrc = (d ? fU : fL) + (size_t)b * CC * NN;
    float* op = out + (size_t)(d * BB + b) * CC * NN;
#pragma unroll
    for (int mt = 0; mt < 2; mt++) {
        int c0 = c_base + cw + mt * 16 + lr;
        int c1 = c0 + 8;
#pragma unroll
        for (int nt = 0; nt < 4; nt++) {
            int m = m0 + mw + nt * 8 + 2 * lc;
            float2 f0 = *(const float2*)&fsrc[(size_t)c0 * NN + m];
            float2 f1 = *(const float2*)&fsrc[(size_t)c1 * NN + m];
            float2 o0 = make_float2(f0.x + beta * acc[mt][nt][0],
                                    f0.y + beta * acc[mt][nt][1]);
            float2 o1 = make_float2(f1.x + beta * acc[mt][nt][2],
                                    f1.y + beta * acc[mt][nt][3]);
            *(float2*)&op[(size_t)c0 * NN + m] = o0;
            *(float2*)&op[(size_t)c1 * NN + m] = o1;
        }
    }
}

// ---------------------------------------------------------------------------
// Launch: 4 dependent kernels on the default stream (graph-capturable).
// ---------------------------------------------------------------------------
extern "C" void kernel_launch(void* const* d_in, const int* in_sizes, int n_in,
                              void* d_out, int out_size)
{
    (void)in_sizes; (void)n_in; (void)out_size;
    const float* fL  = (const float*)d_in[0];
    const float* fU  = (const float*)d_in[1];
    const float* qLw = (const float*)d_in[2];
    const float* qLb = (const float*)d_in[3];
    const float* kUw = (const float*)d_in[4];
    const float* kUb = (const float*)d_in[5];
    const float* vUw = (const float*)d_in[6];
    const float* vUb = (const float*)d_in[7];
    const float* qUw = (const float*)d_in[8];
    const float* qUb = (const float*)d_in[9];
    const float* kLw = (const float*)d_in[10];
    const float* kLb = (const float*)d_in[11];
    const float* vLw = (const float*)d_in[12];
    const float* vLb = (const float*)d_in[13];
    const float* beta = (const float*)d_in[14];
    float* out = (float*)d_out;

    k_proj<<<dim3(NN / 64, BB), 256>>>(fL, fU, qLw, qLb, kUw, kUb,
                                       qUw, qUb, kLw, kLb);
    k_vconv<<<dim3(NN / 128, GG, 2 * BB), 128>>>(fL, fU, vUw, vUb, vLw, vLb);
    k_softstats<<<dim3(NN / 32, BB, 2), 256>>>();
    k_attn_out_tc<<<dim3(NN / MT, 2, 4), 512>>>(fL, fU, beta, out);
}